// round 14
// baseline (speedup 1.0000x reference)
#include <cuda_runtime.h>
#include <math.h>

#define BATCH     32768
#define IN_DIM    64
#define NUM_BINS  10
#define EMBED_DIM 64
#define NTHRESH   9

#define TPB        256
#define K1_MBLK    512                  // pure minmax blocks
#define K1_MWB     8                    // M dot-product blocks (8*80=640 outputs)
#define K1_GRID    (K1_MBLK + K1_MWB + 1)   // + 1 bins block
#define T1         (K1_MBLK * TPB)      // 131072 threads -> exactly 4 float4 each
#define NV         (BATCH * 16)
#define SLOTS      32
#define K3_BLOCKS  512                  // 4096 warps * 8 rows = 32768

#define E8(x)   x,x,x,x,x,x,x,x
#define E64(x)  E8(x),E8(x),E8(x),E8(x),E8(x),E8(x),E8(x),E8(x)
#define E256(x) E64(x),E64(x),E64(x),E64(x)
#define E1K(x)  E256(x),E256(x),E256(x),E256(x)
#define E2K(x)  E1K(x),E1K(x)

__device__ __forceinline__ unsigned fenc(float f) {
    unsigned u = __float_as_uint(f);
    return (u & 0x80000000u) ? ~u : (u | 0x80000000u);
}
__device__ __forceinline__ float fdec(unsigned e) {
    unsigned u = (e & 0x80000000u) ? (e ^ 0x80000000u) : ~e;
    return __uint_as_float(u);
}

// ---- scratch (device globals; no allocation allowed) ----
__device__ unsigned g_minenc[SLOTS * IN_DIM] = { E2K(0xFF800000u) };  // enc(+INF)
__device__ unsigned g_maxenc[SLOTS * IN_DIM] = { E2K(0x007FFFFFu) };  // enc(-INF)
__device__ float    g_bins[NTHRESH];
__device__ float    g_M[NUM_BINS * EMBED_DIM];
__device__ float4   g_nd4[32];            // per lane: {mn0,dn0,mn1,dn1}
__device__ float2   g_D2[NTHRESH * 32];   // D[k] column pairs
__device__ float2   g_base2[32];          // base pairs

// ============ K1: minmax (512 blk) + M warp-dots (8 blk) + bins (1 blk) =====
__global__ void __launch_bounds__(TPB)
k1_stats(const float4* __restrict__ x4,
         const float*  __restrict__ logits,
         const float*  __restrict__ embed,
         const float*  __restrict__ W) {
    const int tid  = threadIdx.x;
    const int lane = tid & 31;
    const int wrp  = tid >> 5;
    const int b    = blockIdx.x;

    if (b < K1_MBLK) {
        // ---- R2-proven: 4 front-batched float4 loads (col-group = tid%16) ----
        __shared__ float smm[2][8][16][4];
        const int tg = b * TPB + tid;
        float4 v0 = x4[tg];
        float4 v1 = x4[tg + T1];
        float4 v2 = x4[tg + 2 * T1];
        float4 v3 = x4[tg + 3 * T1];

        float mn0 = fminf(fminf(v0.x, v1.x), fminf(v2.x, v3.x));
        float mn1 = fminf(fminf(v0.y, v1.y), fminf(v2.y, v3.y));
        float mn2 = fminf(fminf(v0.z, v1.z), fminf(v2.z, v3.z));
        float mn3 = fminf(fminf(v0.w, v1.w), fminf(v2.w, v3.w));
        float mx0 = fmaxf(fmaxf(v0.x, v1.x), fmaxf(v2.x, v3.x));
        float mx1 = fmaxf(fmaxf(v0.y, v1.y), fmaxf(v2.y, v3.y));
        float mx2 = fmaxf(fmaxf(v0.z, v1.z), fmaxf(v2.z, v3.z));
        float mx3 = fmaxf(fmaxf(v0.w, v1.w), fmaxf(v2.w, v3.w));

        mn0 = fminf(mn0, __shfl_down_sync(0xffffffffu, mn0, 16));
        mn1 = fminf(mn1, __shfl_down_sync(0xffffffffu, mn1, 16));
        mn2 = fminf(mn2, __shfl_down_sync(0xffffffffu, mn2, 16));
        mn3 = fminf(mn3, __shfl_down_sync(0xffffffffu, mn3, 16));
        mx0 = fmaxf(mx0, __shfl_down_sync(0xffffffffu, mx0, 16));
        mx1 = fmaxf(mx1, __shfl_down_sync(0xffffffffu, mx1, 16));
        mx2 = fmaxf(mx2, __shfl_down_sync(0xffffffffu, mx2, 16));
        mx3 = fmaxf(mx3, __shfl_down_sync(0xffffffffu, mx3, 16));
        if (lane < 16) {
            smm[0][wrp][lane][0] = mn0; smm[0][wrp][lane][1] = mn1;
            smm[0][wrp][lane][2] = mn2; smm[0][wrp][lane][3] = mn3;
            smm[1][wrp][lane][0] = mx0; smm[1][wrp][lane][1] = mx1;
            smm[1][wrp][lane][2] = mx2; smm[1][wrp][lane][3] = mx3;
        }
        __syncthreads();
        if (tid < IN_DIM) {
            const int g = tid >> 2, q = tid & 3;
            float a =  INFINITY, c = -INFINITY;
            #pragma unroll
            for (int w = 0; w < 8; w++) {
                a = fminf(a, smm[0][w][g][q]);
                c = fmaxf(c, smm[1][w][g][q]);
            }
            const int slot = (b & (SLOTS - 1)) * IN_DIM + tid;
            atomicMin(&g_minenc[slot], fenc(a));
            atomicMax(&g_maxenc[slot], fenc(c));
        }
    } else if (b < K1_MBLK + K1_MWB) {
        // ---- M[k][f] = embed[k] . W[f] via warp dot products (10 per warp) ----
        const int obase = (b - K1_MBLK) * 80 + wrp * 10;
        const float2* __restrict__ em2 = (const float2*)embed;
        const float2* __restrict__ w2  = (const float2*)W;
        #pragma unroll
        for (int j = 0; j < 10; j++) {
            const int o = obase + j;
            const int k = o >> 6, f = o & 63;
            float2 e  = em2[k * 32 + lane];
            float2 wv = w2[f * 32 + lane];
            float s = fmaf(e.y, wv.y, e.x * wv.x);
            #pragma unroll
            for (int d = 16; d >= 1; d >>= 1)
                s += __shfl_xor_sync(0xffffffffu, s, d);
            if (lane == 0) g_M[o] = s;
        }
    } else {
        // ---- bins: parallel exp across 10 lanes of warp 0 ----
        if (wrp == 0) {
            __shared__ float sE[NUM_BINS];
            float li = (lane < NUM_BINS) ? logits[lane] : -INFINITY;
            float m = li;
            #pragma unroll
            for (int d = 16; d >= 1; d >>= 1)
                m = fmaxf(m, __shfl_xor_sync(0xffffffffu, m, d));
            if (lane < NUM_BINS)
                sE[lane] = (float)exp((double)(li - m));   // correctly-rounded f32
            __syncwarp();
            if (lane == 0) {
                float s = 0.f;
                #pragma unroll
                for (int i = 0; i < NUM_BINS; i++) s += sE[i];   // fixed order
                float cum = 0.f;
                #pragma unroll
                for (int i = 0; i < NUM_BINS; i++) {
                    cum += __fdiv_rn(sE[i], s);                   // IEEE div
                    if (i < NTHRESH) g_bins[i] = cum;
                }
            }
        }
    }
}

// ============ K2: finalize mn/dn (+slot reset) + D/base ====================
__global__ void __launch_bounds__(TPB)
k2_finalize(const float* __restrict__ bias) {
    const int tid = threadIdx.x;

    if (tid < IN_DIM) {
        unsigned emin = 0xFF800000u, emax = 0x007FFFFFu;
        #pragma unroll
        for (int s = 0; s < SLOTS; s++) {
            unsigned a = g_minenc[s * IN_DIM + tid];
            unsigned c = g_maxenc[s * IN_DIM + tid];
            emin = (a < emin) ? a : emin;
            emax = (c > emax) ? c : emax;
            g_minenc[s * IN_DIM + tid] = 0xFF800000u;   // reset for next replay
            g_maxenc[s * IN_DIM + tid] = 0x007FFFFFu;
        }
        float a = fdec(emin), c = fdec(emax);
        float dn = (c - a) + 1e-6f;
        float* nd = (float*)g_nd4;
        nd[(tid >> 1) * 4 + (tid & 1) * 2]     = a;
        nd[(tid >> 1) * 4 + (tid & 1) * 2 + 1] = dn;
        ((float*)g_base2)[tid] = 64.f * (g_M[tid] + bias[tid]);
    }
    {
        float* gD = (float*)g_D2;
        for (int i = tid; i < NTHRESH * 64; i += TPB)
            gD[i] = g_M[i + 64] - g_M[i];
    }
}

// ============ K3: main — 8 rows/warp, MLP=8, 32 warps/SM ====================
__global__ void __launch_bounds__(TPB, 4)
k3_main(const float* __restrict__ x, float* __restrict__ out) {
    const int tid  = threadIdx.x;
    const int lane = tid & 31;
    const int wrp  = tid >> 5;
    const int w    = blockIdx.x * 8 + wrp;     // 0..4095
    const int r    = w * 8;

    __shared__ float2 sD2[NTHRESH * 32];       // block-staged D pairs (288 entries)
    for (int i = tid; i < NTHRESH * 32; i += TPB)   // FIX: 288 > 256, must stride
        sD2[i] = g_D2[i];
    __syncthreads();

    const float4 nd = g_nd4[lane];
    const float mn0 = nd.x, dn0 = nd.y, mn1 = nd.z, dn1 = nd.w;

    float bins[NTHRESH];
    #pragma unroll
    for (int k = 0; k < NTHRESH; k++) bins[k] = g_bins[k];

    const float2 bs = g_base2[lane];

    const float2* __restrict__ xp = (const float2*)x + (size_t)r * 32 + lane;
    float2 v0 = xp[0];
    float2 v1 = xp[32];
    float2 v2 = xp[64];
    float2 v3 = xp[96];
    float2 v4 = xp[128];
    float2 v5 = xp[160];
    float2 v6 = xp[192];
    float2 v7 = xp[224];

    const unsigned KM = 0x4B400000u;
    const float    KC = 12582912.0f;
    float2* op = (float2*)out + (size_t)r * 32 + lane;

    // -------- group A: rows 0..3 --------
    {
        float xa0 = __fdiv_rn(v0.x - mn0, dn0), xa1 = __fdiv_rn(v0.y - mn1, dn1);
        float xb0 = __fdiv_rn(v1.x - mn0, dn0), xb1 = __fdiv_rn(v1.y - mn1, dn1);
        float xc0 = __fdiv_rn(v2.x - mn0, dn0), xc1 = __fdiv_rn(v2.y - mn1, dn1);
        float xd0 = __fdiv_rn(v3.x - mn0, dn0), xd1 = __fdiv_rn(v3.y - mn1, dn1);

        unsigned qa0 = 0, qa1 = 0, qb0 = 0, qb1 = 0;
        unsigned qc0 = 0, qc1 = 0, qd0 = 0, qd1 = 0, q2 = 0;
        #pragma unroll
        for (int k = 0; k < 4; k++) {
            const unsigned wgt = 1u << (8 * k);
            qa0 += (xa0 > bins[k]) ? wgt : 0u;  qa0 += (xa1 > bins[k]) ? wgt : 0u;
            qb0 += (xb0 > bins[k]) ? wgt : 0u;  qb0 += (xb1 > bins[k]) ? wgt : 0u;
            qc0 += (xc0 > bins[k]) ? wgt : 0u;  qc0 += (xc1 > bins[k]) ? wgt : 0u;
            qd0 += (xd0 > bins[k]) ? wgt : 0u;  qd0 += (xd1 > bins[k]) ? wgt : 0u;
        }
        #pragma unroll
        for (int k = 4; k < 8; k++) {
            const unsigned wgt = 1u << (8 * (k - 4));
            qa1 += (xa0 > bins[k]) ? wgt : 0u;  qa1 += (xa1 > bins[k]) ? wgt : 0u;
            qb1 += (xb0 > bins[k]) ? wgt : 0u;  qb1 += (xb1 > bins[k]) ? wgt : 0u;
            qc1 += (xc0 > bins[k]) ? wgt : 0u;  qc1 += (xc1 > bins[k]) ? wgt : 0u;
            qd1 += (xd0 > bins[k]) ? wgt : 0u;  qd1 += (xd1 > bins[k]) ? wgt : 0u;
        }
        q2 += (xa0 > bins[8]) ? 0x00000001u : 0u;  q2 += (xa1 > bins[8]) ? 0x00000001u : 0u;
        q2 += (xb0 > bins[8]) ? 0x00000100u : 0u;  q2 += (xb1 > bins[8]) ? 0x00000100u : 0u;
        q2 += (xc0 > bins[8]) ? 0x00010000u : 0u;  q2 += (xc1 > bins[8]) ? 0x00010000u : 0u;
        q2 += (xd0 > bins[8]) ? 0x01000000u : 0u;  q2 += (xd1 > bins[8]) ? 0x01000000u : 0u;

        qa0 = __reduce_add_sync(0xffffffffu, qa0);
        qa1 = __reduce_add_sync(0xffffffffu, qa1);
        qb0 = __reduce_add_sync(0xffffffffu, qb0);
        qb1 = __reduce_add_sync(0xffffffffu, qb1);
        qc0 = __reduce_add_sync(0xffffffffu, qc0);
        qc1 = __reduce_add_sync(0xffffffffu, qc1);
        qd0 = __reduce_add_sync(0xffffffffu, qd0);
        qd1 = __reduce_add_sync(0xffffffffu, qd1);
        q2  = __reduce_add_sync(0xffffffffu, q2);

        float a0 = bs.x, a1 = bs.y, b0 = bs.x, b1 = bs.y;
        float cc0 = bs.x, cc1 = bs.y, d0 = bs.x, d1 = bs.y;
        #pragma unroll
        for (int k = 0; k < 9; k++) {
            float2 Dk = sD2[k * 32 + lane];
            unsigned ua = (k < 4) ? __byte_perm(qa0, KM, 0x7640 + k)
                        : (k < 8) ? __byte_perm(qa1, KM, 0x7640 + (k - 4))
                                  : __byte_perm(q2,  KM, 0x7640);
            unsigned ub = (k < 4) ? __byte_perm(qb0, KM, 0x7640 + k)
                        : (k < 8) ? __byte_perm(qb1, KM, 0x7640 + (k - 4))
                                  : __byte_perm(q2,  KM, 0x7641);
            unsigned uc = (k < 4) ? __byte_perm(qc0, KM, 0x7640 + k)
                        : (k < 8) ? __byte_perm(qc1, KM, 0x7640 + (k - 4))
                                  : __byte_perm(q2,  KM, 0x7642);
            unsigned ud = (k < 4) ? __byte_perm(qd0, KM, 0x7640 + k)
                        : (k < 8) ? __byte_perm(qd1, KM, 0x7640 + (k - 4))
                                  : __byte_perm(q2,  KM, 0x7643);
            float fa = __uint_as_float(ua) - KC;
            float fb = __uint_as_float(ub) - KC;
            float fc = __uint_as_float(uc) - KC;
            float fd = __uint_as_float(ud) - KC;
            a0  = fmaf(fa, Dk.x, a0);   a1  = fmaf(fa, Dk.y, a1);
            b0  = fmaf(fb, Dk.x, b0);   b1  = fmaf(fb, Dk.y, b1);
            cc0 = fmaf(fc, Dk.x, cc0);  cc1 = fmaf(fc, Dk.y, cc1);
            d0  = fmaf(fd, Dk.x, d0);   d1  = fmaf(fd, Dk.y, d1);
        }
        op[0]  = make_float2(a0, a1);
        op[32] = make_float2(b0, b1);
        op[64] = make_float2(cc0, cc1);
        op[96] = make_float2(d0, d1);
    }

    // -------- group B: rows 4..7 --------
    {
        float xa0 = __fdiv_rn(v4.x - mn0, dn0), xa1 = __fdiv_rn(v4.y - mn1, dn1);
        float xb0 = __fdiv_rn(v5.x - mn0, dn0), xb1 = __fdiv_rn(v5.y - mn1, dn1);
        float xc0 = __fdiv_rn(v6.x - mn0, dn0), xc1 = __fdiv_rn(v6.y - mn1, dn1);
        float xd0 = __fdiv_rn(v7.x - mn0, dn0), xd1 = __fdiv_rn(v7.y - mn1, dn1);

        unsigned qa0 = 0, qa1 = 0, qb0 = 0, qb1 = 0;
        unsigned qc0 = 0, qc1 = 0, qd0 = 0, qd1 = 0, q2 = 0;
        #pragma unroll
        for (int k = 0; k < 4; k++) {
            const unsigned wgt = 1u << (8 * k);
            qa0 += (xa0 > bins[k]) ? wgt : 0u;  qa0 += (xa1 > bins[k]) ? wgt : 0u;
            qb0 += (xb0 > bins[k]) ? wgt : 0u;  qb0 += (xb1 > bins[k]) ? wgt : 0u;
            qc0 += (xc0 > bins[k]) ? wgt : 0u;  qc0 += (xc1 > bins[k]) ? wgt : 0u;
            qd0 += (xd0 > bins[k]) ? wgt : 0u;  qd0 += (xd1 > bins[k]) ? wgt : 0u;
        }
        #pragma unroll
        for (int k = 4; k < 8; k++) {
            const unsigned wgt = 1u << (8 * (k - 4));
            qa1 += (xa0 > bins[k]) ? wgt : 0u;  qa1 += (xa1 > bins[k]) ? wgt : 0u;
            qb1 += (xb0 > bins[k]) ? wgt : 0u;  qb1 += (xb1 > bins[k]) ? wgt : 0u;
            qc1 += (xc0 > bins[k]) ? wgt : 0u;  qc1 += (xc1 > bins[k]) ? wgt : 0u;
            qd1 += (xd0 > bins[k]) ? wgt : 0u;  qd1 += (xd1 > bins[k]) ? wgt : 0u;
        }
        q2 += (xa0 > bins[8]) ? 0x00000001u : 0u;  q2 += (xa1 > bins[8]) ? 0x00000001u : 0u;
        q2 += (xb0 > bins[8]) ? 0x00000100u : 0u;  q2 += (xb1 > bins[8]) ? 0x00000100u : 0u;
        q2 += (xc0 > bins[8]) ? 0x00010000u : 0u;  q2 += (xc1 > bins[8]) ? 0x00010000u : 0u;
        q2 += (xd0 > bins[8]) ? 0x01000000u : 0u;  q2 += (xd1 > bins[8]) ? 0x01000000u : 0u;

        qa0 = __reduce_add_sync(0xffffffffu, qa0);
        qa1 = __reduce_add_sync(0xffffffffu, qa1);
        qb0 = __reduce_add_sync(0xffffffffu, qb0);
        qb1 = __reduce_add_sync(0xffffffffu, qb1);
        qc0 = __reduce_add_sync(0xffffffffu, qc0);
        qc1 = __reduce_add_sync(0xffffffffu, qc1);
        qd0 = __reduce_add_sync(0xffffffffu, qd0);
        qd1 = __reduce_add_sync(0xffffffffu, qd1);
        q2  = __reduce_add_sync(0xffffffffu, q2);

        float a0 = bs.x, a1 = bs.y, b0 = bs.x, b1 = bs.y;
        float cc0 = bs.x, cc1 = bs.y, d0 = bs.x, d1 = bs.y;
        #pragma unroll
        for (int k = 0; k < 9; k++) {
            float2 Dk = sD2[k * 32 + lane];
            unsigned ua = (k < 4) ? __byte_perm(qa0, KM, 0x7640 + k)
                        : (k < 8) ? __byte_perm(qa1, KM, 0x7640 + (k - 4))
                                  : __byte_perm(q2,  KM, 0x7640);
            unsigned ub = (k < 4) ? __byte_perm(qb0, KM, 0x7640 + k)
                        : (k < 8) ? __byte_perm(qb1, KM, 0x7640 + (k - 4))
                                  : __byte_perm(q2,  KM, 0x7641);
            unsigned uc = (k < 4) ? __byte_perm(qc0, KM, 0x7640 + k)
                        : (k < 8) ? __byte_perm(qc1, KM, 0x7640 + (k - 4))
                                  : __byte_perm(q2,  KM, 0x7642);
            unsigned ud = (k < 4) ? __byte_perm(qd0, KM, 0x7640 + k)
                        : (k < 8) ? __byte_perm(qd1, KM, 0x7640 + (k - 4))
                                  : __byte_perm(q2,  KM, 0x7643);
            float fa = __uint_as_float(ua) - KC;
            float fb = __uint_as_float(ub) - KC;
            float fc = __uint_as_float(uc) - KC;
            float fd = __uint_as_float(ud) - KC;
            a0  = fmaf(fa, Dk.x, a0);   a1  = fmaf(fa, Dk.y, a1);
            b0  = fmaf(fb, Dk.x, b0);   b1  = fmaf(fb, Dk.y, b1);
            cc0 = fmaf(fc, Dk.x, cc0);  cc1 = fmaf(fc, Dk.y, cc1);
            d0  = fmaf(fd, Dk.x, d0);   d1  = fmaf(fd, Dk.y, d1);
        }
        op[128] = make_float2(a0, a1);
        op[160] = make_float2(b0, b1);
        op[192] = make_float2(cc0, cc1);
        op[224] = make_float2(d0, d1);
    }
}

extern "C" void kernel_launch(void* const* d_in, const int* in_sizes, int n_in,
                              void* d_out, int out_size) {
    const float* x      = (const float*)d_in[0];
    const float* logits = (const float*)d_in[1];
    const float* embed  = (const float*)d_in[2];
    const float* W      = (const float*)d_in[3];
    const float* bias   = (const float*)d_in[4];
    float* out          = (float*)d_out;

    k1_stats<<<K1_GRID, TPB>>>((const float4*)x, logits, embed, W);
    k2_finalize<<<1, TPB>>>(bias);
    k3_main<<<K3_BLOCKS, TPB>>>(x, out);
}

// round 15
// speedup vs baseline: 1.2937x; 1.2937x over previous
#include <cuda_runtime.h>
#include <math.h>

#define BATCH     32768
#define IN_DIM    64
#define NUM_BINS  10
#define EMBED_DIM 64
#define NTHRESH   9

#define TPB        256
#define K1_MBLK    512                  // pure minmax blocks
#define K1_MWB     8                    // M dot-product blocks (8*80=640 outputs)
#define K1_GRID    (K1_MBLK + K1_MWB + 1)   // + 1 bins block
#define T1         (K1_MBLK * TPB)      // 131072 threads -> exactly 4 float4 each
#define NV         (BATCH * 16)
#define SLOTS      16
#define K3_BLOCKS  1024                 // 8192 warps * 4 rows = 32768

#define E8(x)   x,x,x,x,x,x,x,x
#define E64(x)  E8(x),E8(x),E8(x),E8(x),E8(x),E8(x),E8(x),E8(x)
#define E256(x) E64(x),E64(x),E64(x),E64(x)
#define E1K(x)  E256(x),E256(x),E256(x),E256(x)

__device__ __forceinline__ unsigned fenc(float f) {
    unsigned u = __float_as_uint(f);
    return (u & 0x80000000u) ? ~u : (u | 0x80000000u);
}
__device__ __forceinline__ float fdec(unsigned e) {
    unsigned u = (e & 0x80000000u) ? (e ^ 0x80000000u) : ~e;
    return __uint_as_float(u);
}

// ---- scratch (device globals; no allocation allowed) ----
__device__ unsigned g_minenc[SLOTS * IN_DIM] = { E1K(0xFF800000u) };  // enc(+INF)
__device__ unsigned g_maxenc[SLOTS * IN_DIM] = { E1K(0x007FFFFFu) };  // enc(-INF)
__device__ float    g_bins[NTHRESH];
__device__ float    g_M[NUM_BINS * EMBED_DIM];
__device__ int      g_count;              // K3 completion ticket (reset each launch)

// ============ K1: minmax (512 blk) + M warp-dots (8 blk) + bins (1 blk) =====
__global__ void __launch_bounds__(TPB)
k1_stats(const float4* __restrict__ x4,
         const float*  __restrict__ logits,
         const float*  __restrict__ embed,
         const float*  __restrict__ W) {
    const int tid  = threadIdx.x;
    const int lane = tid & 31;
    const int wrp  = tid >> 5;
    const int b    = blockIdx.x;

    if (b < K1_MBLK) {
        // ---- proven: 4 front-batched float4 loads (col-group = tid%16) ----
        __shared__ float smm[2][8][16][4];
        const int tg = b * TPB + tid;
        float4 v0 = x4[tg];
        float4 v1 = x4[tg + T1];
        float4 v2 = x4[tg + 2 * T1];
        float4 v3 = x4[tg + 3 * T1];

        float mn0 = fminf(fminf(v0.x, v1.x), fminf(v2.x, v3.x));
        float mn1 = fminf(fminf(v0.y, v1.y), fminf(v2.y, v3.y));
        float mn2 = fminf(fminf(v0.z, v1.z), fminf(v2.z, v3.z));
        float mn3 = fminf(fminf(v0.w, v1.w), fminf(v2.w, v3.w));
        float mx0 = fmaxf(fmaxf(v0.x, v1.x), fmaxf(v2.x, v3.x));
        float mx1 = fmaxf(fmaxf(v0.y, v1.y), fmaxf(v2.y, v3.y));
        float mx2 = fmaxf(fmaxf(v0.z, v1.z), fmaxf(v2.z, v3.z));
        float mx3 = fmaxf(fmaxf(v0.w, v1.w), fmaxf(v2.w, v3.w));

        mn0 = fminf(mn0, __shfl_down_sync(0xffffffffu, mn0, 16));
        mn1 = fminf(mn1, __shfl_down_sync(0xffffffffu, mn1, 16));
        mn2 = fminf(mn2, __shfl_down_sync(0xffffffffu, mn2, 16));
        mn3 = fminf(mn3, __shfl_down_sync(0xffffffffu, mn3, 16));
        mx0 = fmaxf(mx0, __shfl_down_sync(0xffffffffu, mx0, 16));
        mx1 = fmaxf(mx1, __shfl_down_sync(0xffffffffu, mx1, 16));
        mx2 = fmaxf(mx2, __shfl_down_sync(0xffffffffu, mx2, 16));
        mx3 = fmaxf(mx3, __shfl_down_sync(0xffffffffu, mx3, 16));
        if (lane < 16) {
            smm[0][wrp][lane][0] = mn0; smm[0][wrp][lane][1] = mn1;
            smm[0][wrp][lane][2] = mn2; smm[0][wrp][lane][3] = mn3;
            smm[1][wrp][lane][0] = mx0; smm[1][wrp][lane][1] = mx1;
            smm[1][wrp][lane][2] = mx2; smm[1][wrp][lane][3] = mx3;
        }
        __syncthreads();
        if (tid < IN_DIM) {
            const int g = tid >> 2, q = tid & 3;
            float a =  INFINITY, c = -INFINITY;
            #pragma unroll
            for (int w = 0; w < 8; w++) {
                a = fminf(a, smm[0][w][g][q]);
                c = fmaxf(c, smm[1][w][g][q]);
            }
            const int slot = (b & (SLOTS - 1)) * IN_DIM + tid;
            atomicMin(&g_minenc[slot], fenc(a));
            atomicMax(&g_maxenc[slot], fenc(c));
        }
    } else if (b < K1_MBLK + K1_MWB) {
        // ---- M[k][f] = embed[k] . W[f] via warp dot products (10 per warp) ----
        const int obase = (b - K1_MBLK) * 80 + wrp * 10;
        const float2* __restrict__ em2 = (const float2*)embed;
        const float2* __restrict__ w2  = (const float2*)W;
        #pragma unroll
        for (int j = 0; j < 10; j++) {
            const int o = obase + j;
            const int k = o >> 6, f = o & 63;
            float2 e  = em2[k * 32 + lane];
            float2 wv = w2[f * 32 + lane];
            float s = fmaf(e.y, wv.y, e.x * wv.x);
            #pragma unroll
            for (int d = 16; d >= 1; d >>= 1)
                s += __shfl_xor_sync(0xffffffffu, s, d);
            if (lane == 0) g_M[o] = s;
        }
    } else {
        // ---- bins: parallel exp across 10 lanes of warp 0 ----
        if (wrp == 0) {
            __shared__ float sE[NUM_BINS];
            float li = (lane < NUM_BINS) ? logits[lane] : -INFINITY;
            float m = li;
            #pragma unroll
            for (int d = 16; d >= 1; d >>= 1)
                m = fmaxf(m, __shfl_xor_sync(0xffffffffu, m, d));
            if (lane < NUM_BINS)
                sE[lane] = (float)exp((double)(li - m));   // correctly-rounded f32
            __syncwarp();
            if (lane == 0) {
                float s = 0.f;
                #pragma unroll
                for (int i = 0; i < NUM_BINS; i++) s += sE[i];   // fixed order
                float cum = 0.f;
                #pragma unroll
                for (int i = 0; i < NUM_BINS; i++) {
                    cum += __fdiv_rn(sE[i], s);                   // IEEE div
                    if (i < NTHRESH) g_bins[i] = cum;
                }
            }
        }
    }
}

// ============ K3: finalize-in-prologue + 4 rows/warp main + slot reset ======
__global__ void __launch_bounds__(TPB)
k3_main(const float* __restrict__ x, const float* __restrict__ bias,
        float* __restrict__ out) {
    const int tid  = threadIdx.x;
    const int lane = tid & 31;
    const int wrp  = tid >> 5;
    const int r    = (blockIdx.x * 8 + wrp) * 4;

    __shared__ unsigned sFold[2][TPB];
    __shared__ float    sNd[IN_DIM * 2];        // float4-per-lane {mn0,dn0,mn1,dn1}
    __shared__ float2   sD2[NTHRESH * 32];      // D[k] column pairs
    __shared__ float2   sBase[32];

    // ---- prologue: fold slots -> mn/dn; D; base (all from L2) ----
    {
        const int col = tid & 63, sub = tid >> 6;    // 4 threads per column
        unsigned emin = 0xFF800000u, emax = 0x007FFFFFu;
        #pragma unroll
        for (int s = sub; s < SLOTS; s += 4) {
            unsigned a = g_minenc[s * IN_DIM + col];
            unsigned c = g_maxenc[s * IN_DIM + col];
            emin = (a < emin) ? a : emin;
            emax = (c > emax) ? c : emax;
        }
        sFold[0][tid] = emin;
        sFold[1][tid] = emax;
    }
    {
        float* gD = (float*)sD2;
        for (int i = tid; i < NTHRESH * 64; i += TPB)
            gD[i] = g_M[i + 64] - g_M[i];
        if (tid < 64)
            ((float*)sBase)[tid] = 64.f * (g_M[tid] + bias[tid]);
    }
    __syncthreads();
    if (tid < IN_DIM) {
        unsigned emin = sFold[0][tid], emax = sFold[1][tid];
        #pragma unroll
        for (int s = 1; s < 4; s++) {
            unsigned a = sFold[0][s * IN_DIM + tid];
            unsigned c = sFold[1][s * IN_DIM + tid];
            emin = (a < emin) ? a : emin;
            emax = (c > emax) ? c : emax;
        }
        float a = fdec(emin), c = fdec(emax);
        sNd[(tid >> 1) * 4 + (tid & 1) * 2]     = a;               // mn
        sNd[(tid >> 1) * 4 + (tid & 1) * 2 + 1] = (c - a) + 1e-6f; // dn
    }
    __syncthreads();

    // ---- main: 4 rows per warp (proven body) ----
    const float4 nd = *(const float4*)&sNd[lane * 4];
    const float mn0 = nd.x, dn0 = nd.y, mn1 = nd.z, dn1 = nd.w;

    float bins[NTHRESH];
    #pragma unroll
    for (int k = 0; k < NTHRESH; k++) bins[k] = g_bins[k];

    const float2 bs = sBase[lane];

    const float2* __restrict__ xp = (const float2*)x + (size_t)r * 32 + lane;
    float2 v0 = xp[0];
    float2 v1 = xp[32];
    float2 v2 = xp[64];
    float2 v3 = xp[96];

    float xa0 = __fdiv_rn(v0.x - mn0, dn0), xa1 = __fdiv_rn(v0.y - mn1, dn1);
    float xb0 = __fdiv_rn(v1.x - mn0, dn0), xb1 = __fdiv_rn(v1.y - mn1, dn1);
    float xc0 = __fdiv_rn(v2.x - mn0, dn0), xc1 = __fdiv_rn(v2.y - mn1, dn1);
    float xd0 = __fdiv_rn(v3.x - mn0, dn0), xd1 = __fdiv_rn(v3.y - mn1, dn1);

    unsigned qa0 = 0, qa1 = 0, qb0 = 0, qb1 = 0;
    unsigned qc0 = 0, qc1 = 0, qd0 = 0, qd1 = 0, q2 = 0;
    #pragma unroll
    for (int k = 0; k < 4; k++) {
        const unsigned wgt = 1u << (8 * k);
        qa0 += (xa0 > bins[k]) ? wgt : 0u;  qa0 += (xa1 > bins[k]) ? wgt : 0u;
        qb0 += (xb0 > bins[k]) ? wgt : 0u;  qb0 += (xb1 > bins[k]) ? wgt : 0u;
        qc0 += (xc0 > bins[k]) ? wgt : 0u;  qc0 += (xc1 > bins[k]) ? wgt : 0u;
        qd0 += (xd0 > bins[k]) ? wgt : 0u;  qd0 += (xd1 > bins[k]) ? wgt : 0u;
    }
    #pragma unroll
    for (int k = 4; k < 8; k++) {
        const unsigned wgt = 1u << (8 * (k - 4));
        qa1 += (xa0 > bins[k]) ? wgt : 0u;  qa1 += (xa1 > bins[k]) ? wgt : 0u;
        qb1 += (xb0 > bins[k]) ? wgt : 0u;  qb1 += (xb1 > bins[k]) ? wgt : 0u;
        qc1 += (xc0 > bins[k]) ? wgt : 0u;  qc1 += (xc1 > bins[k]) ? wgt : 0u;
        qd1 += (xd0 > bins[k]) ? wgt : 0u;  qd1 += (xd1 > bins[k]) ? wgt : 0u;
    }
    q2 += (xa0 > bins[8]) ? 0x00000001u : 0u;  q2 += (xa1 > bins[8]) ? 0x00000001u : 0u;
    q2 += (xb0 > bins[8]) ? 0x00000100u : 0u;  q2 += (xb1 > bins[8]) ? 0x00000100u : 0u;
    q2 += (xc0 > bins[8]) ? 0x00010000u : 0u;  q2 += (xc1 > bins[8]) ? 0x00010000u : 0u;
    q2 += (xd0 > bins[8]) ? 0x01000000u : 0u;  q2 += (xd1 > bins[8]) ? 0x01000000u : 0u;

    qa0 = __reduce_add_sync(0xffffffffu, qa0);
    qa1 = __reduce_add_sync(0xffffffffu, qa1);
    qb0 = __reduce_add_sync(0xffffffffu, qb0);
    qb1 = __reduce_add_sync(0xffffffffu, qb1);
    qc0 = __reduce_add_sync(0xffffffffu, qc0);
    qc1 = __reduce_add_sync(0xffffffffu, qc1);
    qd0 = __reduce_add_sync(0xffffffffu, qd0);
    qd1 = __reduce_add_sync(0xffffffffu, qd1);
    q2  = __reduce_add_sync(0xffffffffu, q2);

    const unsigned KM = 0x4B400000u;
    const float    KC = 12582912.0f;

    float a0 = bs.x, a1 = bs.y, b0 = bs.x, b1 = bs.y;
    float cc0 = bs.x, cc1 = bs.y, d0 = bs.x, d1 = bs.y;
    #pragma unroll
    for (int k = 0; k < 9; k++) {
        float2 Dk = sD2[k * 32 + lane];
        unsigned ua = (k < 4) ? __byte_perm(qa0, KM, 0x7640 + k)
                    : (k < 8) ? __byte_perm(qa1, KM, 0x7640 + (k - 4))
                              : __byte_perm(q2,  KM, 0x7640);
        unsigned ub = (k < 4) ? __byte_perm(qb0, KM, 0x7640 + k)
                    : (k < 8) ? __byte_perm(qb1, KM, 0x7640 + (k - 4))
                              : __byte_perm(q2,  KM, 0x7641);
        unsigned uc = (k < 4) ? __byte_perm(qc0, KM, 0x7640 + k)
                    : (k < 8) ? __byte_perm(qc1, KM, 0x7640 + (k - 4))
                              : __byte_perm(q2,  KM, 0x7642);
        unsigned ud = (k < 4) ? __byte_perm(qd0, KM, 0x7640 + k)
                    : (k < 8) ? __byte_perm(qd1, KM, 0x7640 + (k - 4))
                              : __byte_perm(q2,  KM, 0x7643);
        float fa = __uint_as_float(ua) - KC;
        float fb = __uint_as_float(ub) - KC;
        float fc = __uint_as_float(uc) - KC;
        float fd = __uint_as_float(ud) - KC;
        a0  = fmaf(fa, Dk.x, a0);   a1  = fmaf(fa, Dk.y, a1);
        b0  = fmaf(fb, Dk.x, b0);   b1  = fmaf(fb, Dk.y, b1);
        cc0 = fmaf(fc, Dk.x, cc0);  cc1 = fmaf(fc, Dk.y, cc1);
        d0  = fmaf(fd, Dk.x, d0);   d1  = fmaf(fd, Dk.y, d1);
    }
    float2* op = (float2*)out + (size_t)r * 32 + lane;
    op[0]  = make_float2(a0, a1);
    op[32] = make_float2(b0, b1);
    op[64] = make_float2(cc0, cc1);
    op[96] = make_float2(d0, d1);

    // ---- epilogue: last-finishing block resets slots for next graph replay ----
    __syncthreads();          // all this block's slot reads are done (prologue)
    __shared__ int s_ticket;
    if (tid == 0) s_ticket = atomicAdd(&g_count, 1);
    __syncthreads();
    if (s_ticket == K3_BLOCKS - 1) {
        for (int i = tid; i < SLOTS * IN_DIM; i += TPB) {
            g_minenc[i] = 0xFF800000u;
            g_maxenc[i] = 0x007FFFFFu;
        }
        if (tid == 0) g_count = 0;
    }
}

extern "C" void kernel_launch(void* const* d_in, const int* in_sizes, int n_in,
                              void* d_out, int out_size) {
    const float* x      = (const float*)d_in[0];
    const float* logits = (const float*)d_in[1];
    const float* embed  = (const float*)d_in[2];
    const float* W      = (const float*)d_in[3];
    const float* bias   = (const float*)d_in[4];
    float* out          = (float*)d_out;

    k1_stats<<<K1_GRID, TPB>>>((const float4*)x, logits, embed, W);
    k3_main<<<K3_BLOCKS, TPB>>>(x, bias, out);
}